// round 16
// baseline (speedup 1.0000x reference)
#include <cuda_runtime.h>
#include <cuda_bf16.h>
#include <math.h>

#define B_ 512
#define HID 512
#define VOC 4096
#define NOBJ 3
#define FEATIN 2048
#define FEATSZ 512
#define MAXLEN 40
#define TSTEPS 38
#define SOS_IDX 1
#define EOS_IDX 2
#define FTDIM (NOBJ*(FEATSZ+1))
#define LANGN ((long long)B_*MAXLEN*VOC)
#define NVT 32
#define NB 352
#define NT 128

__device__ float g_EW[VOC*3*HID];
__device__ float g_fe[B_*NOBJ*FEATSZ];
__device__ float g_ft[B_*FTDIM];
__device__ float g_h[2][B_*HID];
__device__ float g_gh[B_*3*HID];
__device__ __nv_bfloat16 g_hb[3][B_*HID];
__device__ __nv_bfloat16 g_wb[3][VOC*HID];
__device__ __nv_bfloat16 g_vb[3][3*HID*HID];
__device__ float g_pm[B_*NVT];
__device__ float g_pse[B_*NVT];
__device__ int g_pa[B_*NVT];
__device__ int g_done[B_];
__device__ int g_len[B_];
__device__ unsigned g_bcnt;
__device__ volatile unsigned g_bgen;

typedef unsigned long long u64;
typedef unsigned u32;
__device__ __forceinline__ u64 pk2(float x,float y){u64 r;asm("mov.b64 %0,{%1,%2};":"=l"(r):"f"(x),"f"(y));return r;}
__device__ __forceinline__ u64 dup2(float x){u64 r;asm("mov.b64 %0,{%1,%1};":"=l"(r):"f"(x));return r;}
__device__ __forceinline__ u64 f2fma(u64 a,u64 b,u64 c){u64 d;asm("fma.rn.f32x2 %0,%1,%2,%3;":"=l"(d):"l"(a),"l"(b),"l"(c));return d;}
__device__ __forceinline__ float2 up2(u64 v){float lo,hi;asm("mov.b64 {%0,%1},%2;":"=f"(lo),"=f"(hi):"l"(v));float2 f;f.x=lo;f.y=hi;return f;}
__device__ __forceinline__ u32 su32(const void*p){return (u32)__cvta_generic_to_shared(p);}
__device__ __forceinline__ void cpa16(u32 d,const void*s){asm volatile("cp.async.cg.shared.global [%0], [%1], 16;"::"r"(d),"l"(s):"memory");}
#define MMA(c,a,b) asm volatile("mma.sync.aligned.m16n8k16.row.col.f32.bf16.bf16.f32 {%0,%1,%2,%3},{%4,%5,%6,%7},{%8,%9},{%0,%1,%2,%3};" \
  :"+f"((c)[0]),"+f"((c)[1]),"+f"((c)[2]),"+f"((c)[3]) \
  :"r"((a)[0]),"r"((a)[1]),"r"((a)[2]),"r"((a)[3]),"r"((b)[0]),"r"((b)[1]))

__device__ __forceinline__ void gridbar(){
    __threadfence(); __syncthreads();
    if (threadIdx.x==0){
        unsigned my=g_bgen, t=atomicAdd(&g_bcnt,1u);
        if (t==NB-1){ g_bcnt=0u; __threadfence(); g_bgen=my+1u; }
        else { while (g_bgen==my){} __threadfence(); }
    }
    __syncthreads();
}
__device__ __forceinline__ void split3(float v,size_t i,__nv_bfloat16*p0,__nv_bfloat16*p1,__nv_bfloat16*p2){
    __nv_bfloat16 b0=__float2bfloat16(v); float r1=v-__bfloat162float(b0);
    __nv_bfloat16 b1=__float2bfloat16(r1);
    p0[i]=b0; p1[i]=b1; p2[i]=__float2bfloat16(r1-__bfloat162float(b1));
}

// fp32 prologue 64x64 tile (128 thr, 8m x 4n) — verbatim known-good core
__device__ void gemm64(const float* A,int lda,const float* W,int ldw,const float* bias,
                       float* C,int ldc,int K,int bm,int bn,char* smx)
{
    float (*As)[68]=(float(*)[68])smx; float (*Ws)[132]=(float(*)[132])(smx+4352);
    const int tid=threadIdx.x, tx=tid&15, ty8=(tid>>4)<<3, lk=tid&15, lm0=(tid>>4)<<3;
    u64 acc[8][2];
#pragma unroll
    for(int i=0;i<8;i++){acc[i][0]=0;acc[i][1]=0;}
    __syncthreads();
    for(int kt=0;kt<K;kt+=16){
        const bool ok=(kt+lk)<K;
#pragma unroll
        for(int i=0;i<8;i++){int m=lm0+i;
            As[lk][m]=ok?A[(size_t)(bm+m)*lda+kt+lk]:0.f;
            Ws[lk][m]=ok?W[(size_t)(bn+m)*ldw+kt+lk]:0.f;}
        __syncthreads();
#pragma unroll
        for(int k=0;k<16;k++){
            float4 a0=*(const float4*)&As[k][ty8], a1=*(const float4*)&As[k][ty8+4];
            float4 w0=*(const float4*)&Ws[k][tx<<2];
            u64 b0=pk2(w0.x,w0.y),b1=pk2(w0.z,w0.w);
            u64 A0=dup2(a0.x),A1=dup2(a0.y),A2=dup2(a0.z),A3=dup2(a0.w);
            u64 A4=dup2(a1.x),A5=dup2(a1.y),A6=dup2(a1.z),A7=dup2(a1.w);
            acc[0][0]=f2fma(A0,b0,acc[0][0]);acc[0][1]=f2fma(A0,b1,acc[0][1]);
            acc[1][0]=f2fma(A1,b0,acc[1][0]);acc[1][1]=f2fma(A1,b1,acc[1][1]);
            acc[2][0]=f2fma(A2,b0,acc[2][0]);acc[2][1]=f2fma(A2,b1,acc[2][1]);
            acc[3][0]=f2fma(A3,b0,acc[3][0]);acc[3][1]=f2fma(A3,b1,acc[3][1]);
            acc[4][0]=f2fma(A4,b0,acc[4][0]);acc[4][1]=f2fma(A4,b1,acc[4][1]);
            acc[5][0]=f2fma(A5,b0,acc[5][0]);acc[5][1]=f2fma(A5,b1,acc[5][1]);
            acc[6][0]=f2fma(A6,b0,acc[6][0]);acc[6][1]=f2fma(A6,b1,acc[6][1]);
            acc[7][0]=f2fma(A7,b0,acc[7][0]);acc[7][1]=f2fma(A7,b1,acc[7][1]);
        }
        __syncthreads();
    }
    const int n0=bn+(tx<<2);
    float bb0=0,bb1=0,bb2=0,bb3=0;
    if(bias){bb0=bias[n0];bb1=bias[n0+1];bb2=bias[n0+2];bb3=bias[n0+3];}
#pragma unroll
    for(int r=0;r<8;r++){float2 c0=up2(acc[r][0]),c1=up2(acc[r][1]);
        float* cp=C+(size_t)(bm+ty8+r)*ldc+n0;
        cp[0]=c0.x+bb0;cp[1]=c0.y+bb1;cp[2]=c1.x+bb2;cp[3]=c1.y+bb3;}
}

// online-softmax partial merge
__device__ __forceinline__ void omerge(float&m,int&a,float&s,float m2,int a2,float s2){
    if(m2>m||(m2==m&&a2<a)){ s=s2+s*__expf(m-m2); m=m2; a=a2; }
    else s=s+s2*__expf(m2-m);
}

// HMMA tile 64x128 x K512, 6-term bf16 split; 4 warps of 32x64
__device__ void tc_tile(int islog,int bm,int bn,
    const __nv_bfloat16* B0,const __nv_bfloat16* B1,const __nv_bfloat16* B2,
    const float* bias,const float* gum,int vt,
    char* smx,float (*rm2)[2],int (*ra2)[2],float (*rs2)[2])
{
    const int tid=threadIdx.x, lane=tid&31, wid=tid>>5;
    const int wr=wid>>1, wc=wid&1, gr=lane>>2, cq=lane&3;
    const __nv_bfloat16* Bs[3]={B0,B1,B2};
    const int tiq[6]={0,0,1,1,0,2}, tjq[6]={0,1,0,1,2,0};
    float acc[2][8][4];
#pragma unroll
    for(int i=0;i<2;i++)
#pragma unroll
        for(int j=0;j<8;j++)
#pragma unroll
            for(int k=0;k<4;k++) acc[i][j][k]=0.f;

    const u32 smb=su32(smx);
    for(int kc=0;kc<16;kc++){
#pragma unroll
        for(int s=0;s<3;s++){
            { int r=tid>>1, j=(tid&1)*2;
              u32 d=smb + (u32)s*5120u + (u32)r*80u + (u32)j*16u;
              const char* sp=(const char*)(g_hb[s]+(size_t)(bm+r)*512+kc*32)+j*16;
              cpa16(d,sp); cpa16(d+16,sp+16); }
            { u32 d=smb+15360u + (u32)s*10240u + (u32)tid*80u;
              const char* sp=(const char*)(Bs[s]+(size_t)(bn+tid)*512+kc*32);
              cpa16(d,sp); cpa16(d+16,sp+16); cpa16(d+32,sp+32); cpa16(d+48,sp+48); }
        }
        asm volatile("cp.async.commit_group;":::"memory");
        asm volatile("cp.async.wait_group 0;":::"memory");
        __syncthreads();
#pragma unroll
        for(int q=0;q<6;q++){
            const char* pA = smx + tiq[q]*5120 + (wr*32+gr)*80 + cq*4;
            const char* pB = smx + 15360 + tjq[q]*10240 + (wc*64+gr)*80 + cq*4;
#pragma unroll
            for(int kk=0;kk<2;kk++){
                const int ko=kk*32;
                u32 a[2][4], b[8][2];
#pragma unroll
                for(int mt=0;mt<2;mt++){
                    const char* p = pA + mt*1280 + ko;
                    a[mt][0]=*(const u32*)p; a[mt][1]=*(const u32*)(p+640);
                    a[mt][2]=*(const u32*)(p+16); a[mt][3]=*(const u32*)(p+656);
                }
#pragma unroll
                for(int nt=0;nt<8;nt++){
                    const char* p = pB + nt*640 + ko;
                    b[nt][0]=*(const u32*)p; b[nt][1]=*(const u32*)(p+16);
                }
#pragma unroll
                for(int mt=0;mt<2;mt++)
#pragma unroll
                    for(int nt=0;nt<8;nt++) MMA(acc[mt][nt],a[mt],b[nt]);
            }
        }
        __syncthreads();
    }

    if(islog){
        float ob[8][2]; // out_b pairs per nt
#pragma unroll
        for(int nt=0;nt<8;nt++){
            float2 o=*(const float2*)&bias[bn+wc*64+nt*8+cq*2];
            ob[nt][0]=o.x; ob[nt][1]=o.y;
        }
#pragma unroll
        for(int rs=0;rs<4;rs++){
            const int mt=rs>>1, hi=rs&1;
            const int rloc=wr*32+mt*16+gr+hi*8;
            const float* gr_=gum+(size_t)(bm+rloc)*VOC;
            float m=-3.0e38f, s=0.f; int a=0;
#pragma unroll
            for(int nt=0;nt<8;nt++){
                const int c=bn+wc*64+nt*8+cq*2;
                float2 g=*(const float2*)&gr_[c];
                float v0=acc[mt][nt][hi*2]+ob[nt][0]+g.x;
                float v1=acc[mt][nt][hi*2+1]+ob[nt][1]+g.y;
                if(v0>m){s=s*__expf(m-v0)+1.f;m=v0;a=c;}else s+=__expf(v0-m);
                if(v1>m){s=s*__expf(m-v1)+1.f;m=v1;a=c+1;}else s+=__expf(v1-m);
            }
#pragma unroll
            for(int off=1;off<4;off<<=1){
                float m2=__shfl_xor_sync(0xffffffffu,m,off);
                int   a2=__shfl_xor_sync(0xffffffffu,a,off);
                float s2=__shfl_xor_sync(0xffffffffu,s,off);
                omerge(m,a,s,m2,a2,s2);
            }
            if(cq==0){ rm2[rloc][wc]=m; ra2[rloc][wc]=a; rs2[rloc][wc]=s; }
        }
        __syncthreads();
        if(tid<64){
            float m=rm2[tid][0]; int a=ra2[tid][0]; float s=rs2[tid][0];
            omerge(m,a,s,rm2[tid][1],ra2[tid][1],rs2[tid][1]);
            const int b=bm+tid;
            g_pm[b*NVT+vt]=m; g_pa[b*NVT+vt]=a; g_pse[b*NVT+vt]=s;
        }
        __syncthreads();
    } else {
#pragma unroll
        for(int mt=0;mt<2;mt++){
            const int r0=bm+wr*32+mt*16+gr;
#pragma unroll
            for(int nt=0;nt<8;nt++){
                const int c=bn+wc*64+nt*8+cq*2;
                float2 bh=*(const float2*)&bias[c];
                float2 o0,o1;
                o0.x=acc[mt][nt][0]+bh.x; o0.y=acc[mt][nt][1]+bh.y;
                o1.x=acc[mt][nt][2]+bh.x; o1.y=acc[mt][nt][3]+bh.y;
                *(float2*)&g_gh[(size_t)r0*1536+c]=o0;
                *(float2*)&g_gh[(size_t)(r0+8)*1536+c]=o1;
            }
        }
    }
}

__device__ void phase_Y(int t,const float* hin,float* hout,const float* bih,
                        float* lang,int* yp,float* ys)
{
    const int row0=blockIdx.x<<1, tid=threadIdx.x, wid=tid>>5, lane=tid&31;
    if (wid<2){
        const int row=row0+wid; int A; float spv;
        if (t>0){
            float m=g_pm[row*NVT+lane]; int a=g_pa[row*NVT+lane]; float s=g_pse[row*NVT+lane];
#pragma unroll
            for(int off=16;off>0;off>>=1){
                float m2=__shfl_xor_sync(0xffffffffu,m,off);
                int a2=__shfl_xor_sync(0xffffffffu,a,off);
                float s2=__shfl_xor_sync(0xffffffffu,s,off);
                omerge(m,a,s,m2,a2,s2);
            }
            A=a; float si=1.0f/s; spv=(1.0f+si)-si;
            if(lane==0&&!g_done[row]){
                lang[(size_t)row*MAXLEN*VOC+(size_t)t*VOC+A]=spv;
                g_len[row]+=1;
                if(A==EOS_IDX) g_done[row]=1;
            }
        } else { A=SOS_IDX; spv=1.0f; }
        if(lane==0){yp[wid]=A; ys[wid]=spv;}
    }
    __syncthreads();
    const int p0=yp[0],p1=yp[1]; const float sp0=ys[0],sp1=ys[1];
#pragma unroll
    for(int j=0;j<8;j++){
        const int idx=j*NT+tid, rr=idx>>9, u=idx&511, row=row0+rr;
        const int p=rr?p1:p0; const float spv=rr?sp1:sp0;
        const float* ew=g_EW+(size_t)p*1536;
        const float* gh=g_gh+(size_t)row*1536;
        float gir=fmaf(spv,ew[u],bih[u]);
        float giz=fmaf(spv,ew[u+512],bih[u+512]);
        float gin=fmaf(spv,ew[u+1024],bih[u+1024]);
        float r_=1.0f/(1.0f+expf(-(gir+gh[u])));
        float zz=1.0f/(1.0f+expf(-(giz+gh[u+512])));
        float nn=tanhf(gin+r_*gh[u+1024]);
        float hv=(1.0f-zz)*nn+zz*hin[(size_t)row*HID+u];
        hout[(size_t)row*HID+u]=hv;
        split3(hv,(size_t)row*512+u,g_hb[0],g_hb[1],g_hb[2]);
    }
}

__global__ void __launch_bounds__(NT,3) speaker_all(
    const float* feats,const int* targets,const float* feat_W,const float* feat_b,
    const float* emb_W,const float* init_W,const float* init_b,const float* Wih,
    const float* Whh,const float* bih,const float* bhh,const float* out_W,
    const float* out_b,const float* gumbel,float* out,long long n)
{
    __shared__ char smx[46080];
    __shared__ float rm2[64][2]; __shared__ int ra2[64][2]; __shared__ float rs2[64][2];
    __shared__ int yp[2]; __shared__ float ys[2];
    const int blk=blockIdx.x, tid=threadIdx.x;
    float* h0=g_h[0]; float* h1=g_h[1];

    // P0: zero out; weight splits; fe GEMM; EW GEMM
    {
        const long long n4=n>>2;
        float4 zv; zv.x=zv.y=zv.z=zv.w=0.f;
        for(long long i=(long long)blk*NT+tid;i<n4;i+=(long long)NB*NT) ((float4*)out)[i]=zv;
        if(blk==0&&tid<(int)(n&3)) out[(n&~3LL)+tid]=0.f;
    }
    for(int i=blk*NT+tid;i<VOC*HID;i+=NB*NT) split3(out_W[i],i,g_wb[0],g_wb[1],g_wb[2]);
    for(int i=blk*NT+tid;i<3*HID*HID;i+=NB*NT) split3(Whh[i],i,g_vb[0],g_vb[1],g_vb[2]);
    if(blk<192)
        gemm64(feats,FEATIN,feat_W,FEATIN,feat_b,g_fe,FEATSZ,FEATIN,(blk>>3)<<6,(blk&7)<<6,smx);
    for(int j=blk;j<1536;j+=NB)
        gemm64(emb_W,HID,Wih,HID,(const float*)0,g_EW,3*HID,HID,(j/24)<<6,(j%24)<<6,smx);
    gridbar();

    // P1: ft; init state
    for(int idx=blk*NT+tid;idx<B_*FTDIM;idx+=NB*NT){
        int b=idx/FTDIM,c=idx%FTDIM,o=c/(FEATSZ+1),jj=c%(FEATSZ+1);
        g_ft[idx]=(jj<FEATSZ)?g_fe[((size_t)b*NOBJ+o)*FEATSZ+jj]:((targets[b]==o)?1.f:0.f);
    }
    if(blk<4){int b=blk*NT+tid; g_done[b]=0; g_len[b]=1;
        out[(size_t)b*MAXLEN*VOC+SOS_IDX]=1.0f;}
    gridbar();

    // P2: h0 GEMM
    if(blk<64)
        gemm64(g_ft,FTDIM,init_W,FTDIM,init_b,h0,HID,FTDIM,(blk>>3)<<6,(blk&7)<<6,smx);
    gridbar();

    // P2.5: split h0
    for(int i=blk*NT+tid;i<B_*HID;i+=NB*NT) split3(h0[i],i,g_hb[0],g_hb[1],g_hb[2]);
    gridbar();

    // P3: gh(0) via HMMA tiles
    if(blk>=256){
        int gb=blk-256;
        tc_tile(0,(gb/12)<<6,(gb%12)<<7,g_vb[0],g_vb[1],g_vb[2],bhh,(const float*)0,0,smx,rm2,ra2,rs2);
    }
    gridbar();

    // main loop
    for(int t=0;t<TSTEPS;t++){
        const float* hin=(t&1)?h1:h0; float* hout=(t&1)?h0:h1;
        if(blk<256) phase_Y(t,hin,hout,bih,out,yp,ys);
        gridbar();
        const float* gum=gumbel+(size_t)t*B_*VOC;
        if(blk<256){
            tc_tile(1,(blk>>5)<<6,(blk&31)<<7,g_wb[0],g_wb[1],g_wb[2],out_b,gum,blk&31,smx,rm2,ra2,rs2);
        } else if(t<TSTEPS-1){
            int gb=blk-256;
            tc_tile(0,(gb/12)<<6,(gb%12)<<7,g_vb[0],g_vb[1],g_vb[2],bhh,(const float*)0,0,smx,rm2,ra2,rs2);
        }
        gridbar();
    }

    // epilogue: combine(T-1); finalize
    if(blk<256){
        const int wid=tid>>5, lane=tid&31;
        if(wid<2){
            const int row=(blk<<1)+wid;
            float m=g_pm[row*NVT+lane]; int a=g_pa[row*NVT+lane]; float s=g_pse[row*NVT+lane];
#pragma unroll
            for(int off=16;off>0;off>>=1){
                float m2=__shfl_xor_sync(0xffffffffu,m,off);
                int a2=__shfl_xor_sync(0xffffffffu,a,off);
                float s2=__shfl_xor_sync(0xffffffffu,s,off);
                omerge(m,a,s,m2,a2,s2);
            }
            if(lane==0){
                float si=1.0f/s; float spv=(1.0f+si)-si;
                int L=g_len[row], done=g_done[row];
                if(!done){
                    out[(size_t)row*MAXLEN*VOC+(size_t)TSTEPS*VOC+a]=spv; L+=1;
                    if(a==EOS_IDX) done=1;
                }
                if(!done){
                    out[(size_t)row*MAXLEN*VOC+(size_t)(MAXLEN-1)*VOC+EOS_IDX]=1.0f; L+=1;
                }
                if(LANGN+row<n) out[LANGN+row]=(float)L;
            }
        }
    }
}

extern "C" void kernel_launch(void* const* d_in,const int* in_sizes,int n_in,
                              void* d_out,int out_size)
{
    speaker_all<<<NB,NT>>>(
        (const float*)d_in[0],(const int*)d_in[1],(const float*)d_in[2],(const float*)d_in[3],
        (const float*)d_in[4],(const float*)d_in[5],(const float*)d_in[6],(const float*)d_in[7],
        (const float*)d_in[8],(const float*)d_in[9],(const float*)d_in[10],(const float*)d_in[11],
        (const float*)d_in[12],(const float*)d_in[13],(float*)d_out,(long long)out_size);
}